// round 5
// baseline (speedup 1.0000x reference)
#include <cuda_runtime.h>
#include <cuda_fp16.h>
#include <cstdint>
#include <cstddef>

#define N_NODES 8192
#define F_DIM 512
#define UNITS 256
#define N_GATHER 4096

// Scratch (device globals: no allocation allowed). 16B-aligned for vector access.
__device__ __align__(16) float  g_d[N_NODES];               // 32 KB
__device__ __align__(16) float  g_y32[N_NODES * UNITS];     // 8 MB : y = d[j] * (X@W)
__device__ __align__(16) __half g_y16[N_NODES * UNITS];     // 4 MB : fp16 copy for MMA
__device__ __align__(16) int    g_idx[N_GATHER];            // sanitized gather indices

// ---------------------------------------------------------------------------
// K0: dtype-agnostic gather expansion.
// If the buffer is int64, every odd 32-bit word is a high word of an index in
// [0,8192) -> zero. If int32, 8 random indices all zero has prob ~(1/8192)^8.
// Clamp to [0, N_NODES-1] so a wrong guess yields finite error, never an IMA.
// ---------------------------------------------------------------------------
__global__ void __launch_bounds__(256) k_gather_prep(const int* __restrict__ gather_raw)
{
    __shared__ int is64;
    if (threadIdx.x == 0) {
        int odd_or = 0;
#pragma unroll
        for (int w = 1; w < 16; w += 2) odd_or |= gather_raw[w];
        is64 = (odd_or == 0) ? 1 : 0;
    }
    __syncthreads();
    const int w64 = is64;
    for (int g = threadIdx.x; g < N_GATHER; g += 256) {
        int idx = w64 ? gather_raw[g * 2] : gather_raw[g];
        idx = idx < 0 ? 0 : (idx >= N_NODES ? N_NODES - 1 : idx);
        g_idx[g] = idx;
    }
}

// ---------------------------------------------------------------------------
// K1: d[i] = rsqrt( rowsum(adj[i,:]) + 1 )   (A_tilde = A + I)
// ---------------------------------------------------------------------------
__global__ void __launch_bounds__(256) k_rowsum(const float* __restrict__ adj)
{
    const int row = blockIdx.x;
    const float4* p = reinterpret_cast<const float4*>(adj + (size_t)row * N_NODES);
    float s = 0.f;
#pragma unroll 4
    for (int j = threadIdx.x; j < N_NODES / 4; j += 256) {
        float4 v = p[j];
        s += (v.x + v.y) + (v.z + v.w);
    }
#pragma unroll
    for (int o = 16; o > 0; o >>= 1) s += __shfl_xor_sync(0xffffffffu, s, o);
    __shared__ float ws[8];
    if ((threadIdx.x & 31) == 0) ws[threadIdx.x >> 5] = s;
    __syncthreads();
    if (threadIdx.x == 0) {
        float t = 0.f;
#pragma unroll
        for (int w = 0; w < 8; w++) t += ws[w];
        g_d[row] = rsqrtf(t + 1.0f);
    }
}

// ---------------------------------------------------------------------------
// K2: y = diag(d) * (features @ kernel)  -> g_y32 (fp32) and g_y16 (fp16)
// ---------------------------------------------------------------------------
__global__ void __launch_bounds__(256) k_xw(const float* __restrict__ feat,
                                            const float* __restrict__ wk)
{
    __shared__ float Asm[64][17];
    __shared__ float Bsm[16][64];

    const int tx = threadIdx.x & 15;
    const int ty = threadIdx.x >> 4;
    const int r0 = blockIdx.x * 64;
    const int c0 = blockIdx.y * 64;

    float acc[4][4] = {};

    for (int k0 = 0; k0 < F_DIM; k0 += 16) {
        {
            int row = threadIdx.x >> 2;
            int k4  = (threadIdx.x & 3) * 4;
            float4 v = *reinterpret_cast<const float4*>(
                feat + (size_t)(r0 + row) * F_DIM + k0 + k4);
            Asm[row][k4 + 0] = v.x; Asm[row][k4 + 1] = v.y;
            Asm[row][k4 + 2] = v.z; Asm[row][k4 + 3] = v.w;
        }
        {
            int krow = threadIdx.x >> 4;
            int c4   = (threadIdx.x & 15) * 4;
            float4 v = *reinterpret_cast<const float4*>(
                wk + (size_t)(k0 + krow) * UNITS + c0 + c4);
            *reinterpret_cast<float4*>(&Bsm[krow][c4]) = v;
        }
        __syncthreads();
#pragma unroll
        for (int k = 0; k < 16; k++) {
            float4 b = *reinterpret_cast<float4*>(&Bsm[k][tx * 4]);
            float a0 = Asm[ty * 4 + 0][k];
            float a1 = Asm[ty * 4 + 1][k];
            float a2 = Asm[ty * 4 + 2][k];
            float a3 = Asm[ty * 4 + 3][k];
            acc[0][0] += a0 * b.x; acc[0][1] += a0 * b.y; acc[0][2] += a0 * b.z; acc[0][3] += a0 * b.w;
            acc[1][0] += a1 * b.x; acc[1][1] += a1 * b.y; acc[1][2] += a1 * b.z; acc[1][3] += a1 * b.w;
            acc[2][0] += a2 * b.x; acc[2][1] += a2 * b.y; acc[2][2] += a2 * b.z; acc[2][3] += a2 * b.w;
            acc[3][0] += a3 * b.x; acc[3][1] += a3 * b.y; acc[3][2] += a3 * b.z; acc[3][3] += a3 * b.w;
        }
        __syncthreads();
    }

#pragma unroll
    for (int i = 0; i < 4; i++) {
        int r = r0 + ty * 4 + i;
        float dr = g_d[r];
#pragma unroll
        for (int j = 0; j < 4; j++) {
            int c = c0 + tx * 4 + j;
            float y = dr * acc[i][j];
            g_y32[(size_t)r * UNITS + c] = y;
            g_y16[(size_t)r * UNITS + c] = __float2half_rn(y);
        }
    }
}

// ---------------------------------------------------------------------------
// K3: out[g,:] = relu( d[i] * ( adj[i,:] @ y + y[i,:] ) + bias ),  i = g_idx[g]
// fp16 mma.sync.m16n8k16, fp32 accumulate. BM=64 x BN=128 x BK=32, 8 warps.
// ---------------------------------------------------------------------------
#define K3_BM 64
#define K3_BN 128
#define K3_BK 32
#define AS_STRIDE 40
#define BS_STRIDE 136
#define K_TILES (N_NODES / K3_BK)   // 256

__device__ __forceinline__ uint32_t smem_u32(const void* p)
{
    return (uint32_t)__cvta_generic_to_shared(p);
}
__device__ __forceinline__ void ldsm_x4(uint32_t& r0, uint32_t& r1, uint32_t& r2, uint32_t& r3,
                                        uint32_t a)
{
    asm volatile("ldmatrix.sync.aligned.m8n8.x4.shared.b16 {%0,%1,%2,%3}, [%4];"
                 : "=r"(r0), "=r"(r1), "=r"(r2), "=r"(r3) : "r"(a));
}
__device__ __forceinline__ void ldsm_x4_t(uint32_t& r0, uint32_t& r1, uint32_t& r2, uint32_t& r3,
                                          uint32_t a)
{
    asm volatile("ldmatrix.sync.aligned.m8n8.x4.trans.shared.b16 {%0,%1,%2,%3}, [%4];"
                 : "=r"(r0), "=r"(r1), "=r"(r2), "=r"(r3) : "r"(a));
}
__device__ __forceinline__ void mma16816(float* c,
                                         uint32_t a0, uint32_t a1, uint32_t a2, uint32_t a3,
                                         uint32_t b0, uint32_t b1)
{
    asm volatile(
        "mma.sync.aligned.m16n8k16.row.col.f32.f16.f16.f32 "
        "{%0,%1,%2,%3}, {%4,%5,%6,%7}, {%8,%9}, {%0,%1,%2,%3};"
        : "+f"(c[0]), "+f"(c[1]), "+f"(c[2]), "+f"(c[3])
        : "r"(a0), "r"(a1), "r"(a2), "r"(a3), "r"(b0), "r"(b1));
}

__global__ void __launch_bounds__(256) k_spmm(const float* __restrict__ adj,
                                              const float* __restrict__ bias,
                                              float* __restrict__ out)
{
    __shared__ __align__(16) __half As[2][K3_BM][AS_STRIDE];
    __shared__ __align__(16) __half Bs[2][K3_BK][BS_STRIDE];
    __shared__ int   rowIdx[K3_BM];
    __shared__ float rowD[K3_BM];

    const int tid   = threadIdx.x;
    const int lane  = tid & 31;
    const int warp  = tid >> 5;
    const int warpM = warp >> 2;   // 0..1
    const int warpN = warp & 3;    // 0..3
    const int bx = blockIdx.x;
    const int n0 = blockIdx.y * K3_BN;

    if (tid < K3_BM) {
        int i = g_idx[bx * K3_BM + tid];
        rowIdx[tid] = i;
        rowD[tid]   = g_d[i];
    }
    __syncthreads();

    const int ldRow  = tid >> 3;           // 0..31
    const int ldCol  = (tid & 7) * 4;      // A float4 col
    const int ldColB = (tid & 7) * 8;      // B 8-half col

    float4 ra0, ra1;
    uint4  rb0, rb1;

    auto load_tile = [&](int kt) {
        const int k0 = kt * K3_BK;
        ra0 = *reinterpret_cast<const float4*>(
            adj + (size_t)rowIdx[ldRow] * N_NODES + k0 + ldCol);
        ra1 = *reinterpret_cast<const float4*>(
            adj + (size_t)rowIdx[ldRow + 32] * N_NODES + k0 + ldCol);
        rb0 = *reinterpret_cast<const uint4*>(
            &g_y16[(size_t)(k0 + ldRow) * UNITS + n0 + ldColB]);
        rb1 = *reinterpret_cast<const uint4*>(
            &g_y16[(size_t)(k0 + ldRow) * UNITS + n0 + ldColB + 64]);
    };
    auto store_tile = [&](int buf) {
        *reinterpret_cast<__half2*>(&As[buf][ldRow][ldCol])          = __floats2half2_rn(ra0.x, ra0.y);
        *reinterpret_cast<__half2*>(&As[buf][ldRow][ldCol + 2])      = __floats2half2_rn(ra0.z, ra0.w);
        *reinterpret_cast<__half2*>(&As[buf][ldRow + 32][ldCol])     = __floats2half2_rn(ra1.x, ra1.y);
        *reinterpret_cast<__half2*>(&As[buf][ldRow + 32][ldCol + 2]) = __floats2half2_rn(ra1.z, ra1.w);
        *reinterpret_cast<uint4*>(&Bs[buf][ldRow][ldColB])      = rb0;
        *reinterpret_cast<uint4*>(&Bs[buf][ldRow][ldColB + 64]) = rb1;
    };

    float acc[2][4][4];
#pragma unroll
    for (int mf = 0; mf < 2; mf++)
#pragma unroll
        for (int nf = 0; nf < 4; nf++)
#pragma unroll
            for (int e = 0; e < 4; e++) acc[mf][nf][e] = 0.f;

    load_tile(0);
    store_tile(0);
    __syncthreads();

    int buf = 0;
    for (int kt = 0; kt < K_TILES; ++kt) {
        if (kt + 1 < K_TILES) load_tile(kt + 1);

#pragma unroll
        for (int ks = 0; ks < 2; ++ks) {
            uint32_t af[2][4], bf[2][4];
#pragma unroll
            for (int mf = 0; mf < 2; mf++) {
                int r = warpM * 32 + mf * 16 + (lane & 15);
                int c = ks * 16 + ((lane >> 4) << 3);
                ldsm_x4(af[mf][0], af[mf][1], af[mf][2], af[mf][3],
                        smem_u32(&As[buf][r][c]));
            }
#pragma unroll
            for (int ng = 0; ng < 2; ng++) {
                int r = ks * 16 + (lane & 15);
                int c = warpN * 32 + ng * 16 + ((lane >> 4) << 3);
                ldsm_x4_t(bf[ng][0], bf[ng][1], bf[ng][2], bf[ng][3],
                          smem_u32(&Bs[buf][r][c]));
            }
#pragma unroll
            for (int mf = 0; mf < 2; mf++)
#pragma unroll
                for (int nf = 0; nf < 4; nf++)
                    mma16816(acc[mf][nf],
                             af[mf][0], af[mf][1], af[mf][2], af[mf][3],
                             bf[nf >> 1][(nf & 1) * 2], bf[nf >> 1][(nf & 1) * 2 + 1]);
        }

        if (kt + 1 < K_TILES) {
            __syncthreads();
            store_tile(buf ^ 1);
            __syncthreads();
            buf ^= 1;
        }
    }

    // Epilogue: out = relu( d_i * (acc + y32[i,c]) + bias )
    const int groupID = lane >> 2;
    const int tid4    = lane & 3;
#pragma unroll
    for (int mf = 0; mf < 2; mf++) {
#pragma unroll
        for (int nf = 0; nf < 4; nf++) {
            int c = n0 + warpN * 32 + nf * 8 + tid4 * 2;
            float bv0 = bias[c], bv1 = bias[c + 1];
#pragma unroll
            for (int h = 0; h < 2; h++) {
                int rl = warpM * 32 + mf * 16 + groupID + h * 8;
                int g  = bx * K3_BM + rl;
                int i  = rowIdx[rl];
                float di = rowD[rl];
                float v0 = di * (acc[mf][nf][h * 2 + 0] + g_y32[(size_t)i * UNITS + c]) + bv0;
                float v1 = di * (acc[mf][nf][h * 2 + 1] + g_y32[(size_t)i * UNITS + c + 1]) + bv1;
                out[(size_t)g * UNITS + c]     = fmaxf(v0, 0.f);
                out[(size_t)g * UNITS + c + 1] = fmaxf(v1, 0.f);
            }
        }
    }
}

// ---------------------------------------------------------------------------
// Launch — inputs resolved BY ELEMENT COUNT (order-proof); all 5 sizes distinct.
// ---------------------------------------------------------------------------
extern "C" void kernel_launch(void* const* d_in, const int* in_sizes, int n_in,
                              void* d_out, int out_size)
{
    (void)out_size;
    const float* adj    = nullptr;
    const int*   gather = nullptr;   // raw words; dtype resolved on-device
    const float* feat   = nullptr;
    const float* wk     = nullptr;
    const float* bias   = nullptr;

    for (int i = 0; i < n_in; i++) {
        switch (in_sizes[i]) {
            case 67108864: adj    = (const float*)d_in[i]; break;
            case 4096:     gather = (const int*)d_in[i];   break;
            case 4194304:  feat   = (const float*)d_in[i]; break;
            case 131072:   wk     = (const float*)d_in[i]; break;
            case 256:      bias   = (const float*)d_in[i]; break;
            default: break;
        }
    }
    float* out = (float*)d_out;

    k_gather_prep<<<1, 256>>>(gather);
    k_rowsum<<<N_NODES, 256>>>(adj);
    k_xw<<<dim3(N_NODES / 64, UNITS / 64), 256>>>(feat, wk);
    k_spmm<<<dim3(N_GATHER / K3_BM, UNITS / K3_BN), 256>>>(adj, bias, out);
}

// round 7
// speedup vs baseline: 1.7079x; 1.7079x over previous
#include <cuda_runtime.h>
#include <cuda_fp16.h>
#include <cstdint>
#include <cstddef>

#define N_NODES 8192
#define F_DIM 512
#define UNITS 256
#define N_GATHER 4096

// Device-global scratch (no allocation allowed)
__device__ __align__(16) float  g_d[N_NODES];                    // 32 KB
__device__ __align__(16) float  g_y32[N_NODES * UNITS];          // 8 MB
__device__ __align__(16) __half g_y16[N_NODES * UNITS];          // 4 MB
__device__ __align__(16) __half g_f16[N_NODES * F_DIM];          // 8 MB   fp16 features
__device__ __align__(16) __half g_w16[F_DIM * UNITS];            // 256 KB fp16 kernel
__device__ __align__(16) __half g_adj16[(size_t)N_NODES * N_NODES]; // 128 MB fp16 adj
__device__ __align__(16) int    g_idx[N_GATHER];

// ---------------------------------------------------------------------------
// helpers
// ---------------------------------------------------------------------------
__device__ __forceinline__ uint32_t f2h2(float a, float b)
{
    __half2 h = __floats2half2_rn(a, b);
    return *reinterpret_cast<uint32_t*>(&h);
}
__device__ __forceinline__ uint32_t smem_u32(const void* p)
{
    return (uint32_t)__cvta_generic_to_shared(p);
}
__device__ __forceinline__ void cp16(void* sdst, const void* gsrc)
{
    asm volatile("cp.async.cg.shared.global [%0], [%1], 16;"
                 :: "r"(smem_u32(sdst)), "l"(gsrc));
}
#define CP_COMMIT() asm volatile("cp.async.commit_group;" ::)
#define CP_WAIT(n)  asm volatile("cp.async.wait_group %0;" :: "n"(n))

__device__ __forceinline__ void ldsm_x4(uint32_t& r0, uint32_t& r1, uint32_t& r2, uint32_t& r3,
                                        uint32_t a)
{
    asm volatile("ldmatrix.sync.aligned.m8n8.x4.shared.b16 {%0,%1,%2,%3}, [%4];"
                 : "=r"(r0), "=r"(r1), "=r"(r2), "=r"(r3) : "r"(a));
}
__device__ __forceinline__ void ldsm_x4_t(uint32_t& r0, uint32_t& r1, uint32_t& r2, uint32_t& r3,
                                          uint32_t a)
{
    asm volatile("ldmatrix.sync.aligned.m8n8.x4.trans.shared.b16 {%0,%1,%2,%3}, [%4];"
                 : "=r"(r0), "=r"(r1), "=r"(r2), "=r"(r3) : "r"(a));
}
__device__ __forceinline__ void mma16816(float* c,
                                         uint32_t a0, uint32_t a1, uint32_t a2, uint32_t a3,
                                         uint32_t b0, uint32_t b1)
{
    asm volatile(
        "mma.sync.aligned.m16n8k16.row.col.f32.f16.f16.f32 "
        "{%0,%1,%2,%3}, {%4,%5,%6,%7}, {%8,%9}, {%0,%1,%2,%3};"
        : "+f"(c[0]), "+f"(c[1]), "+f"(c[2]), "+f"(c[3])
        : "r"(a0), "r"(a1), "r"(a2), "r"(a3), "r"(b0), "r"(b1));
}

// ---------------------------------------------------------------------------
// K0: dtype-agnostic gather expansion (int64 vs int32 detected on-device).
// ---------------------------------------------------------------------------
__global__ void __launch_bounds__(256) k_gather_prep(const int* __restrict__ gather_raw)
{
    __shared__ int is64;
    if (threadIdx.x == 0) {
        int odd_or = 0;
#pragma unroll
        for (int w = 1; w < 16; w += 2) odd_or |= gather_raw[w];
        is64 = (odd_or == 0) ? 1 : 0;
    }
    __syncthreads();
    const int w64 = is64;
    for (int g = threadIdx.x; g < N_GATHER; g += 256) {
        int idx = w64 ? gather_raw[g * 2] : gather_raw[g];
        idx = idx < 0 ? 0 : (idx >= N_NODES ? N_NODES - 1 : idx);
        g_idx[g] = idx;
    }
}

// ---------------------------------------------------------------------------
// K0b: transcode features and kernel to fp16 (4 elems/thread).
// blocks 0..4095 -> feat, blocks 4096..4223 -> wk
// ---------------------------------------------------------------------------
__global__ void __launch_bounds__(256) k_cvt(const float* __restrict__ feat,
                                             const float* __restrict__ wk)
{
    int b = blockIdx.x;
    if (b < 4096) {
        int base = b * 1024 + threadIdx.x * 4;
        float4 v = *reinterpret_cast<const float4*>(feat + base);
        uint2 w;
        w.x = f2h2(v.x, v.y);
        w.y = f2h2(v.z, v.w);
        *reinterpret_cast<uint2*>(&g_f16[base]) = w;
    } else {
        int base = (b - 4096) * 1024 + threadIdx.x * 4;
        float4 v = *reinterpret_cast<const float4*>(wk + base);
        uint2 w;
        w.x = f2h2(v.x, v.y);
        w.y = f2h2(v.z, v.w);
        *reinterpret_cast<uint2*>(&g_w16[base]) = w;
    }
}

// ---------------------------------------------------------------------------
// K1: rowsum -> d[i] = rsqrt(sum+1), FUSED with adj -> fp16 transcode.
// ---------------------------------------------------------------------------
__global__ void __launch_bounds__(256) k_rowsum16(const float* __restrict__ adj)
{
    const int row = blockIdx.x;
    const float4* p = reinterpret_cast<const float4*>(adj + (size_t)row * N_NODES);
    uint2* q = reinterpret_cast<uint2*>(&g_adj16[(size_t)row * N_NODES]);
    float s = 0.f;
#pragma unroll 4
    for (int j = threadIdx.x; j < N_NODES / 4; j += 256) {
        float4 v = p[j];
        s += (v.x + v.y) + (v.z + v.w);
        uint2 w;
        w.x = f2h2(v.x, v.y);
        w.y = f2h2(v.z, v.w);
        q[j] = w;
    }
#pragma unroll
    for (int o = 16; o > 0; o >>= 1) s += __shfl_xor_sync(0xffffffffu, s, o);
    __shared__ float ws[8];
    if ((threadIdx.x & 31) == 0) ws[threadIdx.x >> 5] = s;
    __syncthreads();
    if (threadIdx.x == 0) {
        float t = 0.f;
#pragma unroll
        for (int w = 0; w < 8; w++) t += ws[w];
        g_d[row] = rsqrtf(t + 1.0f);
    }
}

// ---------------------------------------------------------------------------
// Shared GEMM geometry: BM=64, BN=64, BK=32, 128 threads (4 warps, 32x32/warp),
// 4-stage cp.async pipeline.  A: [m][k] fp16 row-major, B: [k][n] fp16.
// ---------------------------------------------------------------------------
#define GBM 64
#define GBN 64
#define GBK 32
#define GSTG 4
#define GAS 40   // A smem row stride (halves)
#define GBS 72   // B smem row stride (halves)

// compute one BK=32 slab from stage s; acc[2][4][4]
#define GEMM_COMPUTE(As_, Bs_, s_)                                                  \
    _Pragma("unroll")                                                               \
    for (int ks = 0; ks < 2; ++ks) {                                                \
        uint32_t af[2][4], bf[2][4];                                                \
        _Pragma("unroll")                                                           \
        for (int mf = 0; mf < 2; mf++) {                                            \
            int r = warpM * 32 + mf * 16 + (lane & 15);                             \
            int c = ks * 16 + ((lane >> 4) << 3);                                   \
            ldsm_x4(af[mf][0], af[mf][1], af[mf][2], af[mf][3],                     \
                    smem_u32(&As_[s_][r][c]));                                      \
        }                                                                           \
        _Pragma("unroll")                                                           \
        for (int ng = 0; ng < 2; ng++) {                                            \
            int r = ks * 16 + (lane & 15);                                          \
            int c = warpN * 32 + ng * 16 + ((lane >> 4) << 3);                      \
            ldsm_x4_t(bf[ng][0], bf[ng][1], bf[ng][2], bf[ng][3],                   \
                      smem_u32(&Bs_[s_][r][c]));                                    \
        }                                                                           \
        _Pragma("unroll")                                                           \
        for (int mf = 0; mf < 2; mf++)                                              \
            _Pragma("unroll")                                                       \
            for (int nf = 0; nf < 4; nf++)                                          \
                mma16816(acc[mf][nf],                                               \
                         af[mf][0], af[mf][1], af[mf][2], af[mf][3],                \
                         bf[nf >> 1][(nf & 1) * 2], bf[nf >> 1][(nf & 1) * 2 + 1]); \
    }

// ---------------------------------------------------------------------------
// K2: y = diag(d) * (f16 @ w16), fp32 accum -> g_y32 + g_y16
// grid (128, 4), 128 threads. K iters = 16.
// ---------------------------------------------------------------------------
__global__ void __launch_bounds__(128) k_xw16()
{
    __shared__ __align__(16) __half As[GSTG][GBM][GAS];
    __shared__ __align__(16) __half Bs[GSTG][GBK][GBS];

    const int tid   = threadIdx.x;
    const int lane  = tid & 31;
    const int warp  = tid >> 5;
    const int warpM = warp >> 1;
    const int warpN = warp & 1;
    const int r0 = blockIdx.x * GBM;
    const int c0 = blockIdx.y * GBN;
    const int KT = F_DIM / GBK;   // 16

    const int aRow = tid >> 1;
    const __half* aSrc = g_f16 + (size_t)(r0 + aRow) * F_DIM;

    auto load_stage = [&](int kt, int s) {
        const int k0 = kt * GBK;
#pragma unroll
        for (int j = 0; j < 2; j++) {
            int c = ((tid & 1) * 2 + j) * 8;
            cp16(&As[s][aRow][c], aSrc + k0 + c);
        }
#pragma unroll
        for (int j = 0; j < 2; j++) {
            int chunk = tid * 2 + j;
            int br = chunk >> 3, bc = (chunk & 7) * 8;
            cp16(&Bs[s][br][bc], g_w16 + (size_t)(k0 + br) * UNITS + c0 + bc);
        }
    };

    float acc[2][4][4];
#pragma unroll
    for (int mf = 0; mf < 2; mf++)
#pragma unroll
        for (int nf = 0; nf < 4; nf++)
#pragma unroll
            for (int e = 0; e < 4; e++) acc[mf][nf][e] = 0.f;

#pragma unroll
    for (int s = 0; s < GSTG - 1; s++) { load_stage(s, s); CP_COMMIT(); }

    for (int kt = 0; kt < KT; ++kt) {
        CP_WAIT(GSTG - 2);
        __syncthreads();
        int ktn = kt + GSTG - 1;
        if (ktn < KT) load_stage(ktn, ktn % GSTG);
        CP_COMMIT();
        GEMM_COMPUTE(As, Bs, kt % GSTG);
    }

    const int groupID = lane >> 2;
    const int tid4    = lane & 3;
#pragma unroll
    for (int mf = 0; mf < 2; mf++) {
#pragma unroll
        for (int nf = 0; nf < 4; nf++) {
            int c = c0 + warpN * 32 + nf * 8 + tid4 * 2;
#pragma unroll
            for (int h = 0; h < 2; h++) {
                int r = r0 + warpM * 32 + mf * 16 + groupID + h * 8;
                float dr = g_d[r];
                float v0 = dr * acc[mf][nf][h * 2 + 0];
                float v1 = dr * acc[mf][nf][h * 2 + 1];
                g_y32[(size_t)r * UNITS + c]     = v0;
                g_y32[(size_t)r * UNITS + c + 1] = v1;
                *reinterpret_cast<uint32_t*>(&g_y16[(size_t)r * UNITS + c]) = f2h2(v0, v1);
            }
        }
    }
}

// ---------------------------------------------------------------------------
// K3: out[g,:] = relu( d[i] * ( adj16[i,:] @ y16 + y32[i,:] ) + bias )
// grid (64, 4), 128 threads. K iters = 256. A gathered via rowIdx.
// ---------------------------------------------------------------------------
__global__ void __launch_bounds__(128) k_spmm16(const float* __restrict__ bias,
                                                float* __restrict__ out)
{
    __shared__ __align__(16) __half As[GSTG][GBM][GAS];
    __shared__ __align__(16) __half Bs[GSTG][GBK][GBS];
    __shared__ int   rowIdx[GBM];
    __shared__ float rowD[GBM];

    const int tid   = threadIdx.x;
    const int lane  = tid & 31;
    const int warp  = tid >> 5;
    const int warpM = warp >> 1;
    const int warpN = warp & 1;
    const int m0 = blockIdx.x * GBM;
    const int n0 = blockIdx.y * GBN;
    const int KT = N_NODES / GBK;   // 256

    if (tid < GBM) {
        int i = g_idx[m0 + tid];
        rowIdx[tid] = i;
        rowD[tid]   = g_d[i];
    }
    __syncthreads();

    const int aRow = tid >> 1;
    const __half* aSrc = g_adj16 + (size_t)rowIdx[aRow] * N_NODES;

    auto load_stage = [&](int kt, int s) {
        const int k0 = kt * GBK;
#pragma unroll
        for (int j = 0; j < 2; j++) {
            int c = ((tid & 1) * 2 + j) * 8;
            cp16(&As[s][aRow][c], aSrc + k0 + c);
        }
#pragma unroll
        for (int j = 0; j < 2; j++) {
            int chunk = tid * 2 + j;
            int br = chunk >> 3, bc = (chunk & 7) * 8;
            cp16(&Bs[s][br][bc], g_y16 + (size_t)(k0 + br) * UNITS + n0 + bc);
        }
    };

    float acc[2][4][4];
#pragma unroll
    for (int mf = 0; mf < 2; mf++)
#pragma unroll
        for (int nf = 0; nf < 4; nf++)
#pragma unroll
            for (int e = 0; e < 4; e++) acc[mf][nf][e] = 0.f;

#pragma unroll
    for (int s = 0; s < GSTG - 1; s++) { load_stage(s, s); CP_COMMIT(); }

    for (int kt = 0; kt < KT; ++kt) {
        CP_WAIT(GSTG - 2);
        __syncthreads();
        int ktn = kt + GSTG - 1;
        if (ktn < KT) load_stage(ktn, ktn % GSTG);
        CP_COMMIT();
        GEMM_COMPUTE(As, Bs, kt % GSTG);
    }

    // Epilogue: out = relu( d_i * (acc + y32[i,c]) + bias )
    const int groupID = lane >> 2;
    const int tid4    = lane & 3;
#pragma unroll
    for (int mf = 0; mf < 2; mf++) {
#pragma unroll
        for (int nf = 0; nf < 4; nf++) {
            int c = n0 + warpN * 32 + nf * 8 + tid4 * 2;
            float bv0 = bias[c], bv1 = bias[c + 1];
#pragma unroll
            for (int h = 0; h < 2; h++) {
                int rl = warpM * 32 + mf * 16 + groupID + h * 8;
                int g  = m0 + rl;
                int i  = rowIdx[rl];
                float di = rowD[rl];
                float v0 = di * (acc[mf][nf][h * 2 + 0] + g_y32[(size_t)i * UNITS + c]) + bv0;
                float v1 = di * (acc[mf][nf][h * 2 + 1] + g_y32[(size_t)i * UNITS + c + 1]) + bv1;
                out[(size_t)g * UNITS + c]     = fmaxf(v0, 0.f);
                out[(size_t)g * UNITS + c + 1] = fmaxf(v1, 0.f);
            }
        }
    }
}

// ---------------------------------------------------------------------------
// Launch — inputs resolved BY ELEMENT COUNT (order-proof)
// ---------------------------------------------------------------------------
extern "C" void kernel_launch(void* const* d_in, const int* in_sizes, int n_in,
                              void* d_out, int out_size)
{
    (void)out_size;
    const float* adj    = nullptr;
    const int*   gather = nullptr;
    const float* feat   = nullptr;
    const float* wk     = nullptr;
    const float* bias   = nullptr;

    for (int i = 0; i < n_in; i++) {
        switch (in_sizes[i]) {
            case 67108864: adj    = (const float*)d_in[i]; break;
            case 4096:     gather = (const int*)d_in[i];   break;
            case 4194304:  feat   = (const float*)d_in[i]; break;
            case 131072:   wk     = (const float*)d_in[i]; break;
            case 256:      bias   = (const float*)d_in[i]; break;
            default: break;
        }
    }
    float* out = (float*)d_out;

    k_gather_prep<<<1, 256>>>(gather);
    k_cvt<<<4096 + 128, 256>>>(feat, wk);
    k_rowsum16<<<N_NODES, 256>>>(adj);
    k_xw16<<<dim3(N_NODES / GBM, UNITS / GBN), 128>>>();
    k_spmm16<<<dim3(N_GATHER / GBM, UNITS / GBN), 128>>>(bias, out);
}

// round 10
// speedup vs baseline: 1.9998x; 1.1709x over previous
#include <cuda_runtime.h>
#include <cuda_fp16.h>
#include <cstdint>
#include <cstddef>

#define N_NODES 8192
#define F_DIM 512
#define UNITS 256
#define N_GATHER 4096

// Device-global scratch (no allocation allowed)
__device__ __align__(16) float  g_d[N_NODES];                    // 32 KB
__device__ __align__(16) float  g_y32[N_NODES * UNITS];          // 8 MB
__device__ __align__(16) __half g_y16[N_NODES * UNITS];          // 4 MB
__device__ __align__(16) __half g_f16[N_NODES * F_DIM];          // 8 MB
__device__ __align__(16) __half g_w16[F_DIM * UNITS];            // 256 KB
__device__ __align__(16) __half g_adj16[(size_t)N_NODES * N_NODES]; // 128 MB
__device__ __align__(16) int    g_idx[N_GATHER];
__device__               int    g_rowflag[N_NODES];              // 1 = row is gathered

// ---------------------------------------------------------------------------
// helpers
// ---------------------------------------------------------------------------
__device__ __forceinline__ uint32_t f2h2(float a, float b)
{
    __half2 h = __floats2half2_rn(a, b);
    return *reinterpret_cast<uint32_t*>(&h);
}
__device__ __forceinline__ uint32_t smem_u32(const void* p)
{
    return (uint32_t)__cvta_generic_to_shared(p);
}
__device__ __forceinline__ void cp16(void* sdst, const void* gsrc)
{
    asm volatile("cp.async.cg.shared.global [%0], [%1], 16;"
                 :: "r"(smem_u32(sdst)), "l"(gsrc));
}
#define CP_COMMIT() asm volatile("cp.async.commit_group;" ::)
#define CP_WAIT(n)  asm volatile("cp.async.wait_group %0;" :: "n"(n))

__device__ __forceinline__ void ldsm_x4(uint32_t& r0, uint32_t& r1, uint32_t& r2, uint32_t& r3,
                                        uint32_t a)
{
    asm volatile("ldmatrix.sync.aligned.m8n8.x4.shared.b16 {%0,%1,%2,%3}, [%4];"
                 : "=r"(r0), "=r"(r1), "=r"(r2), "=r"(r3) : "r"(a));
}
__device__ __forceinline__ void ldsm_x4_t(uint32_t& r0, uint32_t& r1, uint32_t& r2, uint32_t& r3,
                                          uint32_t a)
{
    asm volatile("ldmatrix.sync.aligned.m8n8.x4.trans.shared.b16 {%0,%1,%2,%3}, [%4];"
                 : "=r"(r0), "=r"(r1), "=r"(r2), "=r"(r3) : "r"(a));
}
__device__ __forceinline__ void mma16816(float* c,
                                         uint32_t a0, uint32_t a1, uint32_t a2, uint32_t a3,
                                         uint32_t b0, uint32_t b1)
{
    asm volatile(
        "mma.sync.aligned.m16n8k16.row.col.f32.f16.f16.f32 "
        "{%0,%1,%2,%3}, {%4,%5,%6,%7}, {%8,%9}, {%0,%1,%2,%3};"
        : "+f"(c[0]), "+f"(c[1]), "+f"(c[2]), "+f"(c[3])
        : "r"(a0), "r"(a1), "r"(a2), "r"(a3), "r"(b0), "r"(b1));
}

// ---------------------------------------------------------------------------
// K0: dtype-agnostic gather expansion + gathered-row bitmap.
// ---------------------------------------------------------------------------
__global__ void __launch_bounds__(256) k_gather_prep(const int* __restrict__ gather_raw)
{
    for (int r = threadIdx.x; r < N_NODES; r += 256) g_rowflag[r] = 0;
    __syncthreads();

    __shared__ int is64;
    if (threadIdx.x == 0) {
        int odd_or = 0;
#pragma unroll
        for (int w = 1; w < 16; w += 2) odd_or |= gather_raw[w];
        is64 = (odd_or == 0) ? 1 : 0;
    }
    __syncthreads();
    const int w64 = is64;
    for (int g = threadIdx.x; g < N_GATHER; g += 256) {
        int idx = w64 ? gather_raw[g * 2] : gather_raw[g];
        idx = idx < 0 ? 0 : (idx >= N_NODES ? N_NODES - 1 : idx);
        g_idx[g] = idx;
        g_rowflag[idx] = 1;   // benign races: all write 1
    }
}

// ---------------------------------------------------------------------------
// K0b: transcode features and kernel to fp16.
// ---------------------------------------------------------------------------
__global__ void __launch_bounds__(256) k_cvt(const float* __restrict__ feat,
                                             const float* __restrict__ wk)
{
    int b = blockIdx.x;
    if (b < 4096) {
        int base = b * 1024 + threadIdx.x * 4;
        float4 v = *reinterpret_cast<const float4*>(feat + base);
        uint2 w;
        w.x = f2h2(v.x, v.y);
        w.y = f2h2(v.z, v.w);
        *reinterpret_cast<uint2*>(&g_f16[base]) = w;
    } else {
        int base = (b - 4096) * 1024 + threadIdx.x * 4;
        float4 v = *reinterpret_cast<const float4*>(wk + base);
        uint2 w;
        w.x = f2h2(v.x, v.y);
        w.y = f2h2(v.z, v.w);
        *reinterpret_cast<uint2*>(&g_w16[base]) = w;
    }
}

// ---------------------------------------------------------------------------
// K1: rowsum -> d[i] = rsqrt(sum+1); fp16 transcode ONLY for gathered rows.
// ---------------------------------------------------------------------------
__global__ void __launch_bounds__(256) k_rowsum16(const float* __restrict__ adj)
{
    const int row = blockIdx.x;
    const bool wr = (g_rowflag[row] != 0);
    const float4* p = reinterpret_cast<const float4*>(adj + (size_t)row * N_NODES);
    uint2* q = reinterpret_cast<uint2*>(&g_adj16[(size_t)row * N_NODES]);
    float s = 0.f;
    if (wr) {
#pragma unroll 4
        for (int j = threadIdx.x; j < N_NODES / 4; j += 256) {
            float4 v = p[j];
            s += (v.x + v.y) + (v.z + v.w);
            uint2 w;
            w.x = f2h2(v.x, v.y);
            w.y = f2h2(v.z, v.w);
            q[j] = w;
        }
    } else {
#pragma unroll 4
        for (int j = threadIdx.x; j < N_NODES / 4; j += 256) {
            float4 v = p[j];
            s += (v.x + v.y) + (v.z + v.w);
        }
    }
#pragma unroll
    for (int o = 16; o > 0; o >>= 1) s += __shfl_xor_sync(0xffffffffu, s, o);
    __shared__ float ws[8];
    if ((threadIdx.x & 31) == 0) ws[threadIdx.x >> 5] = s;
    __syncthreads();
    if (threadIdx.x == 0) {
        float t = 0.f;
#pragma unroll
        for (int w = 0; w < 8; w++) t += ws[w];
        g_d[row] = rsqrtf(t + 1.0f);
    }
}

// ---------------------------------------------------------------------------
// GEMM geometry: BM=64, BN=64, BK=64, 128 threads (4 warps, 32x32 each),
// 2-stage double buffer.  smem = 2*(64*72 + 64*72)*2B = 36.9 KB (< 48 KB).
// ---------------------------------------------------------------------------
#define GBM 64
#define GBN 64
#define GBK 64
#define GSTG 2
#define GAS 72   // A smem row stride (halves) = 144B
#define GBS 72   // B smem row stride (halves)

// compute one BK=64 slab from stage s_; acc[2][4][4]
#define GEMM_COMPUTE(As_, Bs_, s_)                                                  \
    _Pragma("unroll")                                                               \
    for (int ks = 0; ks < 4; ++ks) {                                                \
        uint32_t af[2][4], bf[2][4];                                                \
        _Pragma("unroll")                                                           \
        for (int mf = 0; mf < 2; mf++) {                                            \
            int r = warpM * 32 + mf * 16 + (lane & 15);                             \
            int c = ks * 16 + ((lane >> 4) << 3);                                   \
            ldsm_x4(af[mf][0], af[mf][1], af[mf][2], af[mf][3],                     \
                    smem_u32(&As_[s_][r][c]));                                      \
        }                                                                           \
        _Pragma("unroll")                                                           \
        for (int ng = 0; ng < 2; ng++) {                                            \
            int r = ks * 16 + (lane & 15);                                          \
            int c = warpN * 32 + ng * 16 + ((lane >> 4) << 3);                      \
            ldsm_x4_t(bf[ng][0], bf[ng][1], bf[ng][2], bf[ng][3],                   \
                      smem_u32(&Bs_[s_][r][c]));                                    \
        }                                                                           \
        _Pragma("unroll")                                                           \
        for (int mf = 0; mf < 2; mf++)                                              \
            _Pragma("unroll")                                                       \
            for (int nf = 0; nf < 4; nf++)                                          \
                mma16816(acc[mf][nf],                                               \
                         af[mf][0], af[mf][1], af[mf][2], af[mf][3],                \
                         bf[nf >> 1][(nf & 1) * 2], bf[nf >> 1][(nf & 1) * 2 + 1]); \
    }

// Double-buffer mainloop (hazard-audited):
//   top sync     = WAR  (all warps finished previous compute before overwrite)
//   always COMMIT (empty group on last iter so CP_WAIT(1) provably drains kt)
//   second sync  = RAW  (stage kt visible to every warp)
#define GEMM_MAINLOOP(KT_)                                                          \
    load_stage(0, 0);                                                               \
    CP_COMMIT();                                                                    \
    for (int kt = 0; kt < (KT_); ++kt) {                                            \
        __syncthreads();                                                            \
        if (kt + 1 < (KT_)) load_stage(kt + 1, (kt + 1) & 1);                       \
        CP_COMMIT();                                                                \
        CP_WAIT(1);                                                                 \
        __syncthreads();                                                            \
        GEMM_COMPUTE(As, Bs, kt & 1);                                               \
    }

// ---------------------------------------------------------------------------
// K2: y = diag(d) * (f16 @ w16)  -> g_y32 + g_y16.  KT = 8.
// ---------------------------------------------------------------------------
__global__ void __launch_bounds__(128) k_xw16()
{
    __shared__ __align__(16) __half As[GSTG][GBM][GAS];
    __shared__ __align__(16) __half Bs[GSTG][GBK][GBS];

    const int tid   = threadIdx.x;
    const int lane  = tid & 31;
    const int warp  = tid >> 5;
    const int warpM = warp >> 1;
    const int warpN = warp & 1;
    const int r0 = blockIdx.x * GBM;
    const int c0 = blockIdx.y * GBN;
    const int KT = F_DIM / GBK;   // 8

    const int lr = tid >> 3;          // 0..15
    const int lc = (tid & 7) * 8;     // 0..56

    auto load_stage = [&](int kt, int s) {
        const int k0 = kt * GBK;
#pragma unroll
        for (int p = 0; p < 4; p++) {
            int row = lr + p * 16;
            cp16(&As[s][row][lc], g_f16 + (size_t)(r0 + row) * F_DIM + k0 + lc);
        }
#pragma unroll
        for (int p = 0; p < 4; p++) {
            int row = lr + p * 16;
            cp16(&Bs[s][row][lc], g_w16 + (size_t)(k0 + row) * UNITS + c0 + lc);
        }
    };

    float acc[2][4][4];
#pragma unroll
    for (int mf = 0; mf < 2; mf++)
#pragma unroll
        for (int nf = 0; nf < 4; nf++)
#pragma unroll
            for (int e = 0; e < 4; e++) acc[mf][nf][e] = 0.f;

    GEMM_MAINLOOP(KT)

    const int groupID = lane >> 2;
    const int tid4    = lane & 3;
#pragma unroll
    for (int mf = 0; mf < 2; mf++) {
#pragma unroll
        for (int nf = 0; nf < 4; nf++) {
            int c = c0 + warpN * 32 + nf * 8 + tid4 * 2;
#pragma unroll
            for (int h = 0; h < 2; h++) {
                int r = r0 + warpM * 32 + mf * 16 + groupID + h * 8;
                float dr = g_d[r];
                float v0 = dr * acc[mf][nf][h * 2 + 0];
                float v1 = dr * acc[mf][nf][h * 2 + 1];
                g_y32[(size_t)r * UNITS + c]     = v0;
                g_y32[(size_t)r * UNITS + c + 1] = v1;
                *reinterpret_cast<uint32_t*>(&g_y16[(size_t)r * UNITS + c]) = f2h2(v0, v1);
            }
        }
    }
}

// ---------------------------------------------------------------------------
// K3: out[g,:] = relu( d[i] * ( adj16[i,:] @ y16 + y32[i,:] ) + bias ).  KT = 128.
// ---------------------------------------------------------------------------
__global__ void __launch_bounds__(128) k_spmm16(const float* __restrict__ bias,
                                                float* __restrict__ out)
{
    __shared__ __align__(16) __half As[GSTG][GBM][GAS];
    __shared__ __align__(16) __half Bs[GSTG][GBK][GBS];
    __shared__ int   rowIdx[GBM];
    __shared__ float rowD[GBM];

    const int tid   = threadIdx.x;
    const int lane  = tid & 31;
    const int warp  = tid >> 5;
    const int warpM = warp >> 1;
    const int warpN = warp & 1;
    const int m0 = blockIdx.x * GBM;
    const int n0 = blockIdx.y * GBN;
    const int KT = N_NODES / GBK;   // 128

    if (tid < GBM) {
        int i = g_idx[m0 + tid];
        rowIdx[tid] = i;
        rowD[tid]   = g_d[i];
    }
    __syncthreads();

    const int lr = tid >> 3;
    const int lc = (tid & 7) * 8;
    const __half* aSrc[4];
#pragma unroll
    for (int p = 0; p < 4; p++)
        aSrc[p] = g_adj16 + (size_t)rowIdx[lr + p * 16] * N_NODES + lc;

    auto load_stage = [&](int kt, int s) {
        const int k0 = kt * GBK;
#pragma unroll
        for (int p = 0; p < 4; p++)
            cp16(&As[s][lr + p * 16][lc], aSrc[p] + k0);
#pragma unroll
        for (int p = 0; p < 4; p++) {
            int row = lr + p * 16;
            cp16(&Bs[s][row][lc], g_y16 + (size_t)(k0 + row) * UNITS + n0 + lc);
        }
    };

    float acc[2][4][4];
#pragma unroll
    for (int mf = 0; mf < 2; mf++)
#pragma unroll
        for (int nf = 0; nf < 4; nf++)
#pragma unroll
            for (int e = 0; e < 4; e++) acc[mf][nf][e] = 0.f;

    GEMM_MAINLOOP(KT)

    // Epilogue: out = relu( d_i * (acc + y32[i,c]) + bias )
    const int groupID = lane >> 2;
    const int tid4    = lane & 3;
#pragma unroll
    for (int mf = 0; mf < 2; mf++) {
#pragma unroll
        for (int nf = 0; nf < 4; nf++) {
            int c = n0 + warpN * 32 + nf * 8 + tid4 * 2;
            float bv0 = bias[c], bv1 = bias[c + 1];
#pragma unroll
            for (int h = 0; h < 2; h++) {
                int rl = warpM * 32 + mf * 16 + groupID + h * 8;
                int g  = m0 + rl;
                int i  = rowIdx[rl];
                float di = rowD[rl];
                float v0 = di * (acc[mf][nf][h * 2 + 0] + g_y32[(size_t)i * UNITS + c]) + bv0;
                float v1 = di * (acc[mf][nf][h * 2 + 1] + g_y32[(size_t)i * UNITS + c + 1]) + bv1;
                out[(size_t)g * UNITS + c]     = fmaxf(v0, 0.f);
                out[(size_t)g * UNITS + c + 1] = fmaxf(v1, 0.f);
            }
        }
    }
}

// ---------------------------------------------------------------------------
// Launch — inputs resolved BY ELEMENT COUNT (order-proof)
// ---------------------------------------------------------------------------
extern "C" void kernel_launch(void* const* d_in, const int* in_sizes, int n_in,
                              void* d_out, int out_size)
{
    (void)out_size;
    const float* adj    = nullptr;
    const int*   gather = nullptr;
    const float* feat   = nullptr;
    const float* wk     = nullptr;
    const float* bias   = nullptr;

    for (int i = 0; i < n_in; i++) {
        switch (in_sizes[i]) {
            case 67108864: adj    = (const float*)d_in[i]; break;
            case 4096:     gather = (const int*)d_in[i];   break;
            case 4194304:  feat   = (const float*)d_in[i]; break;
            case 131072:   wk     = (const float*)d_in[i]; break;
            case 256:      bias   = (const float*)d_in[i]; break;
            default: break;
        }
    }
    float* out = (float*)d_out;

    k_gather_prep<<<1, 256>>>(gather);
    k_cvt<<<4096 + 128, 256>>>(feat, wk);
    k_rowsum16<<<N_NODES, 256>>>(adj);
    k_xw16<<<dim3(N_NODES / GBM, UNITS / GBN), 128>>>();
    k_spmm16<<<dim3(N_GATHER / GBM, UNITS / GBN), 128>>>(bias, out);
}

// round 11
// speedup vs baseline: 2.1388x; 1.0695x over previous
#include <cuda_runtime.h>
#include <cuda_fp16.h>
#include <cstdint>
#include <cstddef>

#define N_NODES 8192
#define F_DIM 512
#define UNITS 256
#define N_GATHER 4096
#define SPLITS 4

// Device-global scratch (no allocation allowed)
__device__ __align__(16) float  g_d[N_NODES];                    // 32 KB
__device__ __align__(16) float  g_y32[N_NODES * UNITS];          // 8 MB
__device__ __align__(16) __half g_y16[N_NODES * UNITS];          // 4 MB
__device__ __align__(16) __half g_f16[N_NODES * F_DIM];          // 8 MB
__device__ __align__(16) __half g_w16[F_DIM * UNITS];            // 256 KB
__device__ __align__(16) __half g_adj16[(size_t)N_NODES * N_NODES]; // 128 MB
__device__ __align__(16) float  g_part[(size_t)SPLITS * N_GATHER * UNITS]; // 16 MB
__device__ __align__(16) int    g_idx[N_GATHER];
__device__               int    g_rowflag[N_NODES];

// ---------------------------------------------------------------------------
// helpers
// ---------------------------------------------------------------------------
__device__ __forceinline__ uint32_t f2h2(float a, float b)
{
    __half2 h = __floats2half2_rn(a, b);
    return *reinterpret_cast<uint32_t*>(&h);
}
__device__ __forceinline__ uint32_t smem_u32(const void* p)
{
    return (uint32_t)__cvta_generic_to_shared(p);
}
__device__ __forceinline__ void cp16(void* sdst, const void* gsrc)
{
    asm volatile("cp.async.cg.shared.global [%0], [%1], 16;"
                 :: "r"(smem_u32(sdst)), "l"(gsrc));
}
#define CP_COMMIT() asm volatile("cp.async.commit_group;" ::)
#define CP_WAIT(n)  asm volatile("cp.async.wait_group %0;" :: "n"(n))

__device__ __forceinline__ void ldsm_x4(uint32_t& r0, uint32_t& r1, uint32_t& r2, uint32_t& r3,
                                        uint32_t a)
{
    asm volatile("ldmatrix.sync.aligned.m8n8.x4.shared.b16 {%0,%1,%2,%3}, [%4];"
                 : "=r"(r0), "=r"(r1), "=r"(r2), "=r"(r3) : "r"(a));
}
__device__ __forceinline__ void ldsm_x4_t(uint32_t& r0, uint32_t& r1, uint32_t& r2, uint32_t& r3,
                                          uint32_t a)
{
    asm volatile("ldmatrix.sync.aligned.m8n8.x4.trans.shared.b16 {%0,%1,%2,%3}, [%4];"
                 : "=r"(r0), "=r"(r1), "=r"(r2), "=r"(r3) : "r"(a));
}
__device__ __forceinline__ void mma16816(float* c,
                                         uint32_t a0, uint32_t a1, uint32_t a2, uint32_t a3,
                                         uint32_t b0, uint32_t b1)
{
    asm volatile(
        "mma.sync.aligned.m16n8k16.row.col.f32.f16.f16.f32 "
        "{%0,%1,%2,%3}, {%4,%5,%6,%7}, {%8,%9}, {%0,%1,%2,%3};"
        : "+f"(c[0]), "+f"(c[1]), "+f"(c[2]), "+f"(c[3])
        : "r"(a0), "r"(a1), "r"(a2), "r"(a3), "r"(b0), "r"(b1));
}

// ---------------------------------------------------------------------------
// K0: dtype-agnostic gather expansion + gathered-row bitmap.
// ---------------------------------------------------------------------------
__global__ void __launch_bounds__(256) k_gather_prep(const int* __restrict__ gather_raw)
{
    for (int r = threadIdx.x; r < N_NODES; r += 256) g_rowflag[r] = 0;
    __syncthreads();

    __shared__ int is64;
    if (threadIdx.x == 0) {
        int odd_or = 0;
#pragma unroll
        for (int w = 1; w < 16; w += 2) odd_or |= gather_raw[w];
        is64 = (odd_or == 0) ? 1 : 0;
    }
    __syncthreads();
    const int w64 = is64;
    for (int g = threadIdx.x; g < N_GATHER; g += 256) {
        int idx = w64 ? gather_raw[g * 2] : gather_raw[g];
        idx = idx < 0 ? 0 : (idx >= N_NODES ? N_NODES - 1 : idx);
        g_idx[g] = idx;
        g_rowflag[idx] = 1;
    }
}

// ---------------------------------------------------------------------------
// K0b: transcode features and kernel to fp16.
// ---------------------------------------------------------------------------
__global__ void __launch_bounds__(256) k_cvt(const float* __restrict__ feat,
                                             const float* __restrict__ wk)
{
    int b = blockIdx.x;
    if (b < 4096) {
        int base = b * 1024 + threadIdx.x * 4;
        float4 v = *reinterpret_cast<const float4*>(feat + base);
        uint2 w;
        w.x = f2h2(v.x, v.y);
        w.y = f2h2(v.z, v.w);
        *reinterpret_cast<uint2*>(&g_f16[base]) = w;
    } else {
        int base = (b - 4096) * 1024 + threadIdx.x * 4;
        float4 v = *reinterpret_cast<const float4*>(wk + base);
        uint2 w;
        w.x = f2h2(v.x, v.y);
        w.y = f2h2(v.z, v.w);
        *reinterpret_cast<uint2*>(&g_w16[base]) = w;
    }
}

// ---------------------------------------------------------------------------
// K1: rowsum -> d[i] = rsqrt(sum+1); fp16 transcode ONLY for gathered rows.
// ---------------------------------------------------------------------------
__global__ void __launch_bounds__(256) k_rowsum16(const float* __restrict__ adj)
{
    const int row = blockIdx.x;
    const bool wr = (g_rowflag[row] != 0);
    const float4* p = reinterpret_cast<const float4*>(adj + (size_t)row * N_NODES);
    uint2* q = reinterpret_cast<uint2*>(&g_adj16[(size_t)row * N_NODES]);
    float s = 0.f;
    if (wr) {
#pragma unroll 4
        for (int j = threadIdx.x; j < N_NODES / 4; j += 256) {
            float4 v = p[j];
            s += (v.x + v.y) + (v.z + v.w);
            uint2 w;
            w.x = f2h2(v.x, v.y);
            w.y = f2h2(v.z, v.w);
            q[j] = w;
        }
    } else {
#pragma unroll 4
        for (int j = threadIdx.x; j < N_NODES / 4; j += 256) {
            float4 v = p[j];
            s += (v.x + v.y) + (v.z + v.w);
        }
    }
#pragma unroll
    for (int o = 16; o > 0; o >>= 1) s += __shfl_xor_sync(0xffffffffu, s, o);
    __shared__ float ws[8];
    if ((threadIdx.x & 31) == 0) ws[threadIdx.x >> 5] = s;
    __syncthreads();
    if (threadIdx.x == 0) {
        float t = 0.f;
#pragma unroll
        for (int w = 0; w < 8; w++) t += ws[w];
        g_d[row] = rsqrtf(t + 1.0f);
    }
}

// ---------------------------------------------------------------------------
// GEMM geometry: BM=64, BN=64, BK=64, 128 threads (4 warps, 32x32 each),
// 2-stage double buffer.  smem = 36.9 KB.
// ---------------------------------------------------------------------------
#define GBM 64
#define GBN 64
#define GBK 64
#define GSTG 2
#define GAS 72
#define GBS 72

#define GEMM_COMPUTE(As_, Bs_, s_)                                                  \
    _Pragma("unroll")                                                               \
    for (int ks = 0; ks < 4; ++ks) {                                                \
        uint32_t af[2][4], bf[2][4];                                                \
        _Pragma("unroll")                                                           \
        for (int mf = 0; mf < 2; mf++) {                                            \
            int r = warpM * 32 + mf * 16 + (lane & 15);                             \
            int c = ks * 16 + ((lane >> 4) << 3);                                   \
            ldsm_x4(af[mf][0], af[mf][1], af[mf][2], af[mf][3],                     \
                    smem_u32(&As_[s_][r][c]));                                      \
        }                                                                           \
        _Pragma("unroll")                                                           \
        for (int ng = 0; ng < 2; ng++) {                                            \
            int r = ks * 16 + (lane & 15);                                          \
            int c = warpN * 32 + ng * 16 + ((lane >> 4) << 3);                      \
            ldsm_x4_t(bf[ng][0], bf[ng][1], bf[ng][2], bf[ng][3],                   \
                      smem_u32(&Bs_[s_][r][c]));                                    \
        }                                                                           \
        _Pragma("unroll")                                                           \
        for (int mf = 0; mf < 2; mf++)                                              \
            _Pragma("unroll")                                                       \
            for (int nf = 0; nf < 4; nf++)                                          \
                mma16816(acc[mf][nf],                                               \
                         af[mf][0], af[mf][1], af[mf][2], af[mf][3],                \
                         bf[nf >> 1][(nf & 1) * 2], bf[nf >> 1][(nf & 1) * 2 + 1]); \
    }

// Double-buffer mainloop (WAR sync / always-commit / RAW sync)
#define GEMM_MAINLOOP(KT_)                                                          \
    load_stage(0, 0);                                                               \
    CP_COMMIT();                                                                    \
    for (int kt = 0; kt < (KT_); ++kt) {                                            \
        __syncthreads();                                                            \
        if (kt + 1 < (KT_)) load_stage(kt + 1, (kt + 1) & 1);                       \
        CP_COMMIT();                                                                \
        CP_WAIT(1);                                                                 \
        __syncthreads();                                                            \
        GEMM_COMPUTE(As, Bs, kt & 1);                                               \
    }

// ---------------------------------------------------------------------------
// K2: y = diag(d) * (f16 @ w16)  -> g_y32 + g_y16.  KT = 8.
// ---------------------------------------------------------------------------
__global__ void __launch_bounds__(128) k_xw16()
{
    __shared__ __align__(16) __half As[GSTG][GBM][GAS];
    __shared__ __align__(16) __half Bs[GSTG][GBK][GBS];

    const int tid   = threadIdx.x;
    const int lane  = tid & 31;
    const int warp  = tid >> 5;
    const int warpM = warp >> 1;
    const int warpN = warp & 1;
    const int r0 = blockIdx.x * GBM;
    const int c0 = blockIdx.y * GBN;
    const int KT = F_DIM / GBK;   // 8

    const int lr = tid >> 3;
    const int lc = (tid & 7) * 8;

    auto load_stage = [&](int kt, int s) {
        const int k0 = kt * GBK;
#pragma unroll
        for (int p = 0; p < 4; p++) {
            int row = lr + p * 16;
            cp16(&As[s][row][lc], g_f16 + (size_t)(r0 + row) * F_DIM + k0 + lc);
        }
#pragma unroll
        for (int p = 0; p < 4; p++) {
            int row = lr + p * 16;
            cp16(&Bs[s][row][lc], g_w16 + (size_t)(k0 + row) * UNITS + c0 + lc);
        }
    };

    float acc[2][4][4];
#pragma unroll
    for (int mf = 0; mf < 2; mf++)
#pragma unroll
        for (int nf = 0; nf < 4; nf++)
#pragma unroll
            for (int e = 0; e < 4; e++) acc[mf][nf][e] = 0.f;

    GEMM_MAINLOOP(KT)

    const int groupID = lane >> 2;
    const int tid4    = lane & 3;
#pragma unroll
    for (int mf = 0; mf < 2; mf++) {
#pragma unroll
        for (int nf = 0; nf < 4; nf++) {
            int c = c0 + warpN * 32 + nf * 8 + tid4 * 2;
#pragma unroll
            for (int h = 0; h < 2; h++) {
                int r = r0 + warpM * 32 + mf * 16 + groupID + h * 8;
                float dr = g_d[r];
                float v0 = dr * acc[mf][nf][h * 2 + 0];
                float v1 = dr * acc[mf][nf][h * 2 + 1];
                g_y32[(size_t)r * UNITS + c]     = v0;
                g_y32[(size_t)r * UNITS + c + 1] = v1;
                *reinterpret_cast<uint32_t*>(&g_y16[(size_t)r * UNITS + c]) = f2h2(v0, v1);
            }
        }
    }
}

// ---------------------------------------------------------------------------
// K3: split-K partial GEMM.  part[z][g][c] = sum_{k in split z} adj16[i,k]*y16[k,c]
// grid (64, 4, SPLITS), 128 threads.  KT per split = 8192/64/SPLITS = 32.
// ---------------------------------------------------------------------------
__global__ void __launch_bounds__(128) k_spmm16_split()
{
    __shared__ __align__(16) __half As[GSTG][GBM][GAS];
    __shared__ __align__(16) __half Bs[GSTG][GBK][GBS];
    __shared__ int rowIdx[GBM];

    const int tid   = threadIdx.x;
    const int lane  = tid & 31;
    const int warp  = tid >> 5;
    const int warpM = warp >> 1;
    const int warpN = warp & 1;
    const int m0 = blockIdx.x * GBM;
    const int n0 = blockIdx.y * GBN;
    const int z  = blockIdx.z;
    const int KT = N_NODES / GBK / SPLITS;   // 32
    const int kbase = z * KT;

    if (tid < GBM) rowIdx[tid] = g_idx[m0 + tid];
    __syncthreads();

    const int lr = tid >> 3;
    const int lc = (tid & 7) * 8;
    const __half* aSrc[4];
#pragma unroll
    for (int p = 0; p < 4; p++)
        aSrc[p] = g_adj16 + (size_t)rowIdx[lr + p * 16] * N_NODES + lc;

    auto load_stage = [&](int kt, int s) {
        const int k0 = (kbase + kt) * GBK;
#pragma unroll
        for (int p = 0; p < 4; p++)
            cp16(&As[s][lr + p * 16][lc], aSrc[p] + k0);
#pragma unroll
        for (int p = 0; p < 4; p++) {
            int row = lr + p * 16;
            cp16(&Bs[s][row][lc], g_y16 + (size_t)(k0 + row) * UNITS + n0 + lc);
        }
    };

    float acc[2][4][4];
#pragma unroll
    for (int mf = 0; mf < 2; mf++)
#pragma unroll
        for (int nf = 0; nf < 4; nf++)
#pragma unroll
            for (int e = 0; e < 4; e++) acc[mf][nf][e] = 0.f;

    GEMM_MAINLOOP(KT)

    // write raw partials (no scaling here)
    float* part = g_part + (size_t)z * N_GATHER * UNITS;
    const int groupID = lane >> 2;
    const int tid4    = lane & 3;
#pragma unroll
    for (int mf = 0; mf < 2; mf++) {
#pragma unroll
        for (int nf = 0; nf < 4; nf++) {
            int c = n0 + warpN * 32 + nf * 8 + tid4 * 2;
#pragma unroll
            for (int h = 0; h < 2; h++) {
                int g = m0 + warpM * 32 + mf * 16 + groupID + h * 8;
                part[(size_t)g * UNITS + c]     = acc[mf][nf][h * 2 + 0];
                part[(size_t)g * UNITS + c + 1] = acc[mf][nf][h * 2 + 1];
            }
        }
    }
}

// ---------------------------------------------------------------------------
// K4: reduce splits + epilogue.
// out[g,c] = relu( d_i * ( sum_z part[z][g][c] + y32[i][c] ) + bias[c] )
// 262144 float4-elements -> 1024 blocks x 256 threads, 1 float4 each.
// ---------------------------------------------------------------------------
__global__ void __launch_bounds__(256) k_reduce(const float* __restrict__ bias,
                                                float* __restrict__ out)
{
    const int t  = blockIdx.x * 256 + threadIdx.x;   // 0 .. 4096*64-1
    const int g  = t >> 6;
    const int c  = (t & 63) * 4;
    const int i  = g_idx[g];
    const float di = g_d[i];

    float4 s = *reinterpret_cast<const float4*>(&g_part[(size_t)g * UNITS + c]);
#pragma unroll
    for (int z = 1; z < SPLITS; z++) {
        const float4 p = *reinterpret_cast<const float4*>(
            &g_part[(size_t)z * N_GATHER * UNITS + (size_t)g * UNITS + c]);
        s.x += p.x; s.y += p.y; s.z += p.z; s.w += p.w;
    }
    const float4 y = *reinterpret_cast<const float4*>(&g_y32[(size_t)i * UNITS + c]);
    const float4 b = *reinterpret_cast<const float4*>(&bias[c]);

    float4 r;
    r.x = fmaxf(di * (s.x + y.x) + b.x, 0.f);
    r.y = fmaxf(di * (s.y + y.y) + b.y, 0.f);
    r.z = fmaxf(di * (s.z + y.z) + b.z, 0.f);
    r.w = fmaxf(di * (s.w + y.w) + b.w, 0.f);
    *reinterpret_cast<float4*>(&out[(size_t)g * UNITS + c]) = r;
}

// ---------------------------------------------------------------------------
// Launch — inputs resolved BY ELEMENT COUNT (order-proof)
// ---------------------------------------------------------------------------
extern "C" void kernel_launch(void* const* d_in, const int* in_sizes, int n_in,
                              void* d_out, int out_size)
{
    (void)out_size;
    const float* adj    = nullptr;
    const int*   gather = nullptr;
    const float* feat   = nullptr;
    const float* wk     = nullptr;
    const float* bias   = nullptr;

    for (int i = 0; i < n_in; i++) {
        switch (in_sizes[i]) {
            case 67108864: adj    = (const float*)d_in[i]; break;
            case 4096:     gather = (const int*)d_in[i];   break;
            case 4194304:  feat   = (const float*)d_in[i]; break;
            case 131072:   wk     = (const float*)d_in[i]; break;
            case 256:      bias   = (const float*)d_in[i]; break;
            default: break;
        }
    }
    float* out = (float*)d_out;

    k_gather_prep<<<1, 256>>>(gather);
    k_cvt<<<4096 + 128, 256>>>(feat, wk);
    k_rowsum16<<<N_NODES, 256>>>(adj);
    k_xw16<<<dim3(N_NODES / GBM, UNITS / GBN), 128>>>();
    k_spmm16_split<<<dim3(N_GATHER / GBM, UNITS / GBN, SPLITS), 128>>>();
    k_reduce<<<(N_GATHER * UNITS / 4) / 256, 256>>>(bias, out);
}